// round 16
// baseline (speedup 1.0000x reference)
#include <cuda_runtime.h>
#include <cuda_fp16.h>
#include <math_constants.h>
#include <cstdint>
#include <cstddef>

// ---------------------------------------------------------------------------
// Problem constants
// ---------------------------------------------------------------------------
#define Dm   512
#define Sm   64
#define Lm   256
#define Fm   2048
#define Hh   64
#define Cc   8
#define Pp   (Sm * Lm)          // 16384 spatial positions
#define EPS  1e-5f

// ---------------------------------------------------------------------------
// Scratch buffers (static device globals -- allocation-free)
// ---------------------------------------------------------------------------
__device__ __align__(256) __half g_tmph[(long)Dm * Pp];      // row_out [c][pos] / col_out,ff2 [pos][c]

// fp16 operands (all single-plane)
__device__ __align__(256) __half g_qkv16[3L * Dm * Pp];      // qkv fp16 [1536][16384]
__device__ __align__(256) __half g_bt [(long)Pp * Dm];       // activation stream [pos][512]
__device__ __align__(256) __half g_ff [(long)Pp * Fm];       // ff1^T [Pp,2048]
__device__ __align__(256) __half g_wr [3 * Dm * Dm];
__device__ __align__(256) __half g_wc [3 * Dm * Dm];
__device__ __align__(256) __half g_f1 [Fm * Dm];
__device__ __align__(256) __half g_f2 [Dm * Fm];
__device__ __align__(256) __half g_qt [(long)Hh * Lm * Dm];  // Q^T per head
__device__ __align__(256) __half g_kt [(long)Hh * Lm * Dm];  // K^T per head
__device__ __align__(256) __half g_p16[(long)Hh * Lm * Lm];  // P [h][i][j]

// ---------------------------------------------------------------------------
// PTX helpers
// ---------------------------------------------------------------------------
__device__ __forceinline__ uint32_t smem_u32(const void* p) {
    uint32_t a;
    asm("{ .reg .u64 t; cvta.to.shared.u64 t, %1; cvt.u32.u64 %0, t; }" : "=r"(a) : "l"(p));
    return a;
}
__device__ __forceinline__ void cpasync16(uint32_t dst, const void* src) {
    asm volatile("cp.async.cg.shared.global [%0], [%1], 16;" :: "r"(dst), "l"(src));
}
__device__ __forceinline__ void cp_commit() {
    asm volatile("cp.async.commit_group;" ::: "memory");
}
template<int N>
__device__ __forceinline__ void cp_wait() {
    asm volatile("cp.async.wait_group %0;" :: "n"(N) : "memory");
}
__device__ __forceinline__ void ldsm4(uint32_t* r, uint32_t addr) {
    asm volatile("ldmatrix.sync.aligned.m8n8.x4.shared.b16 {%0,%1,%2,%3}, [%4];"
                 : "=r"(r[0]), "=r"(r[1]), "=r"(r[2]), "=r"(r[3]) : "r"(addr));
}
__device__ __forceinline__ void mma16816h(float* d, const uint32_t* a, uint32_t b0, uint32_t b1) {
    asm volatile("mma.sync.aligned.m16n8k16.row.col.f32.f16.f16.f32 "
                 "{%0,%1,%2,%3}, {%4,%5,%6,%7}, {%8,%9}, {%0,%1,%2,%3};"
                 : "+f"(d[0]), "+f"(d[1]), "+f"(d[2]), "+f"(d[3])
                 : "r"(a[0]), "r"(a[1]), "r"(a[2]), "r"(a[3]), "r"(b0), "r"(b1));
}

// ---------------------------------------------------------------------------
// Big GEMM: C[M,N] = W[M,K] * B[N,K]^T (+bias), single fp16 pass.
// CTA tile 128x128, BK=64, 3-stage ring (96KB), 8 warps (4m x 2n), 2 CTAs/SM.
//   MODE 0: C fp32 [M,N] + bias.
//   MODE 1: relu(+bias) -> fp16 transposed [N,M].
//   MODE 2: fp16 [M,N] + bias.
//   MODE 3: (+bias) -> fp16 transposed [N,M] (no relu).
// ---------------------------------------------------------------------------
#define MM_SBYTES 32768u
#define MM_SMEM   (3 * MM_SBYTES)

template<int MODE>
__global__ void __launch_bounds__(256, 2)
gemm_mma(const __half* __restrict__ A, const __half* __restrict__ B,
         const float* __restrict__ bias,
         float* __restrict__ C, __half* __restrict__ oH,
         int M, int N, int K)
{
    extern __shared__ char smem[];
    const uint32_t sb = smem_u32(smem);

    const int tid  = threadIdx.x;
    const int wid  = tid >> 5;
    const int lane = tid & 31;
    const int warpM = wid & 3;
    const int warpN = wid >> 2;
    const int bm = blockIdx.x * 128;
    const int bn = blockIdx.y * 128;

    auto load_stage = [&](int st, int it) {
        const uint32_t sbase = sb + st * MM_SBYTES;
        const int k0 = it << 6;
#pragma unroll
        for (int j = 0; j < 4; j++) {
            const int idx = tid + j * 256;
            const int row = idx >> 3;
            const int c   = idx & 7;
            const uint32_t soff = row * 128 + ((c * 16) ^ ((row & 7) << 4));
            cpasync16(sbase +         soff, A + (size_t)(bm + row) * K + k0 + c * 8);
            cpasync16(sbase + 16384 + soff, B + (size_t)(bn + row) * K + k0 + c * 8);
        }
    };

    float acc[2][8][4];
#pragma unroll
    for (int i = 0; i < 2; i++)
#pragma unroll
        for (int j = 0; j < 8; j++)
#pragma unroll
            for (int v = 0; v < 4; v++) acc[i][j][v] = 0.f;

    const int nIter = K >> 6;
    load_stage(0, 0); cp_commit();
    load_stage(1, 1); cp_commit();

    const int rsub  = lane & 15;
    const int khalf = ((lane >> 4) & 1) * 16;
    const int rA = warpM * 32 + rsub;
    const int rB = warpN * 64 + rsub;
    const uint32_t xA = (rA & 7) << 4;
    const uint32_t xB = (rB & 7) << 4;

    for (int it = 0; it < nIter; it++) {
        cp_wait<1>();
        __syncthreads();
        if (it + 2 < nIter) load_stage((it + 2) % 3, it + 2);
        cp_commit();

        const uint32_t sbase = sb + (it % 3) * MM_SBYTES;
        const uint32_t pA = sbase +         rA * 128;
        const uint32_t pB = sbase + 16384 + rB * 128;

#pragma unroll
        for (int q = 0; q < 4; q++) {
            const uint32_t kb = q * 32 + khalf;
            uint32_t ah[2][4], bb[4][4];
#pragma unroll
            for (int mt = 0; mt < 2; mt++)
                ldsm4(ah[mt], pA + mt * 2048 + (kb ^ xA));
#pragma unroll
            for (int g = 0; g < 4; g++)
                ldsm4(bb[g], pB + g * 2048 + (kb ^ xB));
#pragma unroll
            for (int mt = 0; mt < 2; mt++)
#pragma unroll
                for (int nt = 0; nt < 8; nt++) {
                    const int g = nt >> 1, o = nt & 1;
                    mma16816h(acc[mt][nt], ah[mt], bb[g][o], bb[g][o + 2]);
                }
        }
    }
    cp_wait<0>();
    __syncthreads();

    if (MODE == 0) {
#pragma unroll
        for (int mt = 0; mt < 2; mt++) {
            const int r0 = bm + warpM * 32 + mt * 16 + (lane >> 2);
            const float bv0 = bias[r0], bv1 = bias[r0 + 8];
#pragma unroll
            for (int nt = 0; nt < 8; nt++) {
                const int c0 = bn + warpN * 64 + nt * 8 + (lane & 3) * 2;
                float* d = acc[mt][nt];
                *reinterpret_cast<float2*>(&C[(size_t)r0 * N + c0])       = make_float2(d[0] + bv0, d[1] + bv0);
                *reinterpret_cast<float2*>(&C[(size_t)(r0 + 8) * N + c0]) = make_float2(d[2] + bv1, d[3] + bv1);
            }
        }
    } else if (MODE == 2) {
#pragma unroll
        for (int mt = 0; mt < 2; mt++) {
            const int r0 = bm + warpM * 32 + mt * 16 + (lane >> 2);
            const float bv0 = bias[r0], bv1 = bias[r0 + 8];
#pragma unroll
            for (int nt = 0; nt < 8; nt++) {
                const int c0 = bn + warpN * 64 + nt * 8 + (lane & 3) * 2;
                float* d = acc[mt][nt];
                *reinterpret_cast<__half2*>(&oH[(size_t)r0 * N + c0])       = __floats2half2_rn(d[0] + bv0, d[1] + bv0);
                *reinterpret_cast<__half2*>(&oH[(size_t)(r0 + 8) * N + c0]) = __floats2half2_rn(d[2] + bv1, d[3] + bv1);
            }
        }
    } else {
        // MODE 1 / MODE 3: fp16 transposed [N,M], optional relu
        float* T = reinterpret_cast<float*>(smem);   // [128][130]
#pragma unroll
        for (int mt = 0; mt < 2; mt++) {
            const int lr0 = warpM * 32 + mt * 16 + (lane >> 2);
            const float bv0 = bias[bm + lr0], bv1 = bias[bm + lr0 + 8];
#pragma unroll
            for (int nt = 0; nt < 8; nt++) {
                const int lc0 = warpN * 64 + nt * 8 + (lane & 3) * 2;
                float* d = acc[mt][nt];
                float v00 = d[0] + bv0, v01 = d[1] + bv0;
                float v10 = d[2] + bv1, v11 = d[3] + bv1;
                if (MODE == 1) {
                    v00 = fmaxf(v00, 0.f); v01 = fmaxf(v01, 0.f);
                    v10 = fmaxf(v10, 0.f); v11 = fmaxf(v11, 0.f);
                }
                T[lr0 * 130 + lc0]           = v00;
                T[lr0 * 130 + lc0 + 1]       = v01;
                T[(lr0 + 8) * 130 + lc0]     = v10;
                T[(lr0 + 8) * 130 + lc0 + 1] = v11;
            }
        }
        __syncthreads();
        const int mloc = tid & 127;
#pragma unroll 4
        for (int rep = 0; rep < 64; rep++) {
            const int nl = rep * 2 + (tid >> 7);
            oH[(size_t)(bn + nl) * M + bm + mloc] = __float2half(T[mloc * 130 + nl]);
        }
    }
}

// ---------------------------------------------------------------------------
// Row-attention scores + FUSED softmax: per head tile 64(i) x 256(j), K=512.
// ---------------------------------------------------------------------------
#define SC_SBYTES 40960u
#define SC_SMEM   (2 * SC_SBYTES)

__global__ void __launch_bounds__(256, 2)
gemm_scores(const __half* __restrict__ Q, const __half* __restrict__ Kt,
            __half* __restrict__ P)
{
    constexpr int K = 512;
    extern __shared__ char smem[];
    const uint32_t sb = smem_u32(smem);

    const int tid = threadIdx.x, wid = tid >> 5, lane = tid & 31;
    const int warpM = wid & 3;
    const int warpN = wid >> 2;
    const int bm = blockIdx.x * 64;
    const int h = blockIdx.z;
    const __half* A = Q  + (size_t)h * Lm * Dm;
    const __half* B = Kt + (size_t)h * Lm * Dm;

    auto load_stage = [&](int st, int it) {
        const uint32_t sbase = sb + st * SC_SBYTES;
        const int k0 = it << 6;
#pragma unroll
        for (int j = 0; j < 10; j++) {
            const int idx = tid + j * 256;
            if (idx < 512) {
                const int row = idx >> 3, c = idx & 7;
                const uint32_t soff = row * 128 + ((c * 16) ^ ((row & 7) << 4));
                cpasync16(sbase + soff, A + (size_t)(bm + row) * K + k0 + c * 8);
            } else {
                const int i2 = idx - 512;
                const int row = i2 >> 3, c = i2 & 7;
                const uint32_t soff = row * 128 + ((c * 16) ^ ((row & 7) << 4));
                cpasync16(sbase + 8192 + soff, B + (size_t)row * K + k0 + c * 8);
            }
        }
    };

    float acc[16][4];
#pragma unroll
    for (int j = 0; j < 16; j++)
#pragma unroll
        for (int v = 0; v < 4; v++) acc[j][v] = 0.f;

    load_stage(0, 0); cp_commit();
    load_stage(1, 1); cp_commit();

    const int rsub  = lane & 15;
    const int khalf = ((lane >> 4) & 1) * 16;
    const int rA = warpM * 16 + rsub;
    const int rBb = warpN * 128 + rsub;
    const uint32_t xs = (rsub & 7) << 4;

    for (int it = 0; it < 8; it++) {
        cp_wait<1>();
        __syncthreads();

        const uint32_t sbase = sb + (it & 1) * SC_SBYTES;
        const uint32_t pA = sbase +        rA  * 128;
        const uint32_t pB = sbase + 8192 + rBb * 128;

#pragma unroll
        for (int q = 0; q < 4; q++) {
            const uint32_t kb = q * 32 + khalf;
            uint32_t ah[4], bb[8][4];
            ldsm4(ah, pA + (kb ^ xs));
#pragma unroll
            for (int g = 0; g < 8; g++)
                ldsm4(bb[g], pB + g * 2048 + (kb ^ xs));
#pragma unroll
            for (int nt = 0; nt < 16; nt++) {
                const int g = nt >> 1, o = nt & 1;
                mma16816h(acc[nt], ah, bb[g][o], bb[g][o + 2]);
            }
        }
        __syncthreads();
        if (it + 2 < 8) { load_stage(it & 1, it + 2); }
        cp_commit();
    }
    cp_wait<0>();
    __syncthreads();

    float* S = reinterpret_cast<float*>(smem);
    {
        const int r0 = warpM * 16 + (lane >> 2);
#pragma unroll
        for (int nt = 0; nt < 16; nt++) {
            const int c0 = warpN * 128 + nt * 8 + (lane & 3) * 2;
            float* d = acc[nt];
            S[r0 * 260 + c0]           = d[0];
            S[r0 * 260 + c0 + 1]       = d[1];
            S[(r0 + 8) * 260 + c0]     = d[2];
            S[(r0 + 8) * 260 + c0 + 1] = d[3];
        }
    }
    __syncthreads();

#pragma unroll
    for (int rr = 0; rr < 8; rr++) {
        const int r = wid * 8 + rr;
        float v[8];
#pragma unroll
        for (int k = 0; k < 8; k++) v[k] = S[r * 260 + lane + 32 * k];
        float m = v[0];
#pragma unroll
        for (int k = 1; k < 8; k++) m = fmaxf(m, v[k]);
#pragma unroll
        for (int o = 16; o; o >>= 1) m = fmaxf(m, __shfl_xor_sync(0xffffffffu, m, o));
        float s = 0.f;
#pragma unroll
        for (int k = 0; k < 8; k++) { v[k] = __expf(v[k] - m); s += v[k]; }
#pragma unroll
        for (int o = 16; o; o >>= 1) s += __shfl_xor_sync(0xffffffffu, s, o);
        const float inv = 1.f / s;
        __half* dst = P + ((size_t)h * Lm + bm + r) * Lm;
#pragma unroll
        for (int k = 0; k < 8; k++) dst[lane + 32 * k] = __float2half(v[k] * inv);
    }
}

// ---------------------------------------------------------------------------
// Row-attention output: per head, C[m=(c,s), i] = sum_j V[m,j] * P[i,j]. fp16 out
// in [c][pos] layout (consumed by step-5 LN which reads [c][pos]).
// ---------------------------------------------------------------------------
__global__ void __launch_bounds__(256, 2)
gemm_vp(const __half* __restrict__ V, const __half* __restrict__ P,
        __half* __restrict__ O)
{
    constexpr int K = 256;
    extern __shared__ char smem[];
    const uint32_t sb = smem_u32(smem);

    const int tid = threadIdx.x, wid = tid >> 5, lane = tid & 31;
    const int warpM = wid & 3, warpN = wid >> 2;
    const int bm = blockIdx.x * 128, bn = blockIdx.y * 128;
    const int h = blockIdx.z;
    const __half* Av = V + (size_t)h * 8 * Pp;
    const __half* Bp = P + (size_t)h * Lm * Lm;
    __half* C = O + (size_t)h * 8 * Pp;

    auto load_stage = [&](int st, int it) {
        const uint32_t sbase = sb + st * MM_SBYTES;
        const int k0 = it << 6;
#pragma unroll
        for (int j = 0; j < 4; j++) {
            const int idx = tid + j * 256;
            const int row = idx >> 3;
            const int c   = idx & 7;
            const uint32_t soff = row * 128 + ((c * 16) ^ ((row & 7) << 4));
            const int mrow = bm + row;
            const size_t ga = (size_t)(mrow >> 6) * Pp + (mrow & 63) * 256 + k0 + c * 8;
            cpasync16(sbase +         soff, Av + ga);
            cpasync16(sbase + 16384 + soff, Bp + (size_t)(bn + row) * K + k0 + c * 8);
        }
    };

    float acc[2][8][4];
#pragma unroll
    for (int i = 0; i < 2; i++)
#pragma unroll
        for (int j = 0; j < 8; j++)
#pragma unroll
            for (int v = 0; v < 4; v++) acc[i][j][v] = 0.f;

    load_stage(0, 0); cp_commit();
    load_stage(1, 1); cp_commit();

    const int rsub  = lane & 15;
    const int khalf = ((lane >> 4) & 1) * 16;
    const int rA = warpM * 32 + rsub;
    const int rB = warpN * 64 + rsub;
    const uint32_t xA = (rA & 7) << 4;
    const uint32_t xB = (rB & 7) << 4;

    for (int it = 0; it < 4; it++) {
        cp_wait<1>();
        __syncthreads();
        if (it + 2 < 4) load_stage((it + 2) % 3, it + 2);
        cp_commit();

        const uint32_t sbase = sb + (it % 3) * MM_SBYTES;
        const uint32_t pA = sbase +         rA * 128;
        const uint32_t pB = sbase + 16384 + rB * 128;

#pragma unroll
        for (int q = 0; q < 4; q++) {
            const uint32_t kb = q * 32 + khalf;
            uint32_t av[2][4], bb[4][4];
#pragma unroll
            for (int mt = 0; mt < 2; mt++)
                ldsm4(av[mt], pA + mt * 2048 + (kb ^ xA));
#pragma unroll
            for (int g = 0; g < 4; g++)
                ldsm4(bb[g], pB + g * 2048 + (kb ^ xB));
#pragma unroll
            for (int mt = 0; mt < 2; mt++)
#pragma unroll
                for (int nt = 0; nt < 8; nt++) {
                    const int g = nt >> 1, o = nt & 1;
                    mma16816h(acc[mt][nt], av[mt], bb[g][o], bb[g][o + 2]);
                }
        }
    }
    cp_wait<0>();
    __syncthreads();

#pragma unroll
    for (int mt = 0; mt < 2; mt++) {
        const int r0 = bm + warpM * 32 + mt * 16 + (lane >> 2);
        const int r1 = r0 + 8;
        const size_t a0 = (size_t)(r0 >> 6) * Pp + (r0 & 63) * 256;
        const size_t a1 = (size_t)(r1 >> 6) * Pp + (r1 & 63) * 256;
#pragma unroll
        for (int nt = 0; nt < 8; nt++) {
            const int c0 = bn + warpN * 64 + nt * 8 + (lane & 3) * 2;
            float* d = acc[mt][nt];
            *reinterpret_cast<__half2*>(&C[a0 + c0]) = __floats2half2_rn(d[0], d[1]);
            *reinterpret_cast<__half2*>(&C[a1 + c0]) = __floats2half2_rn(d[2], d[3]);
        }
    }
}

// ---------------------------------------------------------------------------
// Merged weight conversion
// ---------------------------------------------------------------------------
#define WN1 (3 * Dm * Dm)
#define WN2 (2 * WN1)
#define WN3 (WN2 + Fm * Dm)
#define WN4 (WN3 + Dm * Fm)

__global__ void convw_all(const float* __restrict__ w_row, const float* __restrict__ w_col,
                          const float* __restrict__ wf1, const float* __restrict__ wf2,
                          __half* __restrict__ owr, __half* __restrict__ owc,
                          __half* __restrict__ of1, __half* __restrict__ of2)
{
    const long i = ((long)blockIdx.x * 256 + threadIdx.x) * 4;
    const float* src; __half* dst; long off;
    if (i < WN1)      { src = w_row; dst = owr; off = 0; }
    else if (i < WN2) { src = w_col; dst = owc; off = WN1; }
    else if (i < WN3) { src = wf1;   dst = of1; off = WN2; }
    else              { src = wf2;   dst = of2; off = WN3; }
    const long j = i - off;
    const float4 v = *reinterpret_cast<const float4*>(src + j);
    *reinterpret_cast<__half2*>(dst + j)     = __floats2half2_rn(v.x, v.y);
    *reinterpret_cast<__half2*>(dst + j + 2) = __floats2half2_rn(v.z, v.w);
}

// act fp32 [K, N] -> fp16 [N, K] (transposed) — only for the initial x
__global__ void __launch_bounds__(256)
convt_kernel(const float* __restrict__ in, __half* __restrict__ oh, int K, int N)
{
    __shared__ float t[32][33];
    const int n0 = blockIdx.x * 32, k0 = blockIdx.y * 32;
    const int tx = threadIdx.x, ty = threadIdx.y;
#pragma unroll
    for (int i = 0; i < 4; i++)
        t[ty + 8 * i][tx] = in[(size_t)(k0 + ty + 8 * i) * N + n0 + tx];
    __syncthreads();
#pragma unroll
    for (int i = 0; i < 4; i++) {
        const int r = ty + 8 * i;
        oh[(size_t)(n0 + r) * K + k0 + tx] = __float2half(t[tx][r]);
    }
}

// Q/K per-head transpose (fp16 in, fp16 out) — half2 vectorized, 64x64 tiles.
__global__ void __launch_bounds__(256)
convtqk_kernel(const __half* __restrict__ qkv,
               __half* __restrict__ qo, __half* __restrict__ ko)
{
    __shared__ __half t[64][66];
    const int h = blockIdx.z >> 1;
    const int isK = blockIdx.z & 1;
    const __half* in = qkv + (isK ? (size_t)Dm * Pp : 0) + (size_t)h * 8 * Pp;
    __half* o = (isK ? ko : qo) + (size_t)h * Lm * Dm;
    const int l0 = blockIdx.x * 64, k0 = blockIdx.y * 64;
    const int tx = threadIdx.x, ty = threadIdx.y;
#pragma unroll
    for (int i = 0; i < 8; i++) {
        const int k = k0 + ty + 8 * i;
        const __half2 v = *reinterpret_cast<const __half2*>(
            &in[(size_t)(k >> 6) * Pp + (k & 63) * 256 + l0 + 2 * tx]);
        t[2 * tx][ty + 8 * i]     = __low2half(v);
        t[2 * tx + 1][ty + 8 * i] = __high2half(v);
    }
    __syncthreads();
#pragma unroll
    for (int i = 0; i < 8; i++) {
        const int r = ty + 8 * i;
        *reinterpret_cast<__half2*>(&o[(size_t)(l0 + r) * Dm + k0 + 2 * tx]) =
            *reinterpret_cast<const __half2*>(&t[r][2 * tx]);
    }
}

// ---------------------------------------------------------------------------
// Step-5 LN (row path): in fp32 [c][pos] + res fp16 [c][pos] -> bt fp16 [pos][c].
// (pos across lanes, as in round-15 — known good)
// ---------------------------------------------------------------------------
__global__ __launch_bounds__(256)
void ln_row_kernel(const float* __restrict__ in, const __half* __restrict__ res,
                   const float* __restrict__ w1, const float* __restrict__ b1,
                   __half* __restrict__ obt)
{
    __shared__ float ss[8][32], ss2[8][32];
    __shared__ __half tbuf[32][514];
    const int tx = threadIdx.x, ty = threadIdx.y;
    const int tid = ty * 32 + tx;
    const int pos0 = blockIdx.x * 32;
    const int pos = pos0 + tx;

    float vals[64];
    float s = 0.f, s2 = 0.f;
#pragma unroll
    for (int i = 0; i < 64; i++) {
        const int c = ty + 8 * i;
        float v = in[(size_t)c * Pp + pos] + __half2float(res[(size_t)c * Pp + pos]);
        vals[i] = v; s += v; s2 += v * v;
    }
    ss[ty][tx] = s; ss2[ty][tx] = s2;
    __syncthreads();
    float st = 0.f, st2 = 0.f;
#pragma unroll
    for (int y = 0; y < 8; y++) { st += ss[y][tx]; st2 += ss2[y][tx]; }
    const float mean = st * (1.f / Dm);
    const float var  = st2 * (1.f / Dm) - mean * mean;
    const float rstd = rsqrtf(var + EPS);

#pragma unroll
    for (int i = 0; i < 64; i++) {
        const int c = ty + 8 * i;
        tbuf[tx][c] = __float2half((vals[i] - mean) * rstd * w1[c] + b1[c]);
    }
    __syncthreads();
#pragma unroll 4
    for (int r = 0; r < 32; r++) {
        const uint32_t val = *reinterpret_cast<const uint32_t*>(&tbuf[r][tid * 2]);
        *reinterpret_cast<uint32_t*>(&obt[(size_t)(pos0 + r) * Dm + tid * 2]) = val;
    }
}

// ---------------------------------------------------------------------------
// ln_t: double LN in [pos][c]. bt += res (both [pos][c] fp16); LN(an2) then
// LN(ln1); write back to bt. Warp-per-position, shfl reductions.
// Block 256 = 8 warps x 4 positions each; grid Pp/32.
// ---------------------------------------------------------------------------
__global__ __launch_bounds__(256)
void ln_t_kernel(__half* __restrict__ bt, const __half* __restrict__ res,
                 const float* __restrict__ w1, const float* __restrict__ b1,
                 const float* __restrict__ w2, const float* __restrict__ b2)
{
    const int lane = threadIdx.x & 31;
    const int warp = threadIdx.x >> 5;

#pragma unroll 1
    for (int p = 0; p < 4; p++) {
        const int pos = blockIdx.x * 32 + warp * 4 + p;
        __half* row = bt + (size_t)pos * Dm;
        const __half* rrow = res + (size_t)pos * Dm;

        float vals[16];
        float s = 0.f, s2 = 0.f;
#pragma unroll
        for (int k = 0; k < 16; k++) {
            const int c = lane + 32 * k;
            const float v = __half2float(row[c]) + __half2float(rrow[c]);
            vals[k] = v; s += v; s2 += v * v;
        }
#pragma unroll
        for (int o = 16; o; o >>= 1) {
            s  += __shfl_xor_sync(0xffffffffu, s,  o);
            s2 += __shfl_xor_sync(0xffffffffu, s2, o);
        }
        {
            const float mean = s * (1.f / Dm);
            const float var  = s2 * (1.f / Dm) - mean * mean;
            const float rstd = rsqrtf(var + EPS);
#pragma unroll
            for (int k = 0; k < 16; k++) {
                const int c = lane + 32 * k;
                vals[k] = (vals[k] - mean) * rstd * w1[c] + b1[c];
            }
        }
        float t = 0.f, t2 = 0.f;
#pragma unroll
        for (int k = 0; k < 16; k++) { t += vals[k]; t2 += vals[k] * vals[k]; }
#pragma unroll
        for (int o = 16; o; o >>= 1) {
            t  += __shfl_xor_sync(0xffffffffu, t,  o);
            t2 += __shfl_xor_sync(0xffffffffu, t2, o);
        }
        {
            const float mean = t * (1.f / Dm);
            const float var  = t2 * (1.f / Dm) - mean * mean;
            const float rstd = rsqrtf(var + EPS);
#pragma unroll
            for (int k = 0; k < 16; k++) {
                const int c = lane + 32 * k;
                row[c] = __float2half((vals[k] - mean) * rstd * w2[c] + b2[c]);
            }
        }
    }
}

// ---------------------------------------------------------------------------
// ln_final: LN in [pos][c] (bt + res fp16), output fp32 [c][pos] via smem-staged
// transpose. Block 256 = 8 warps x 4 positions; smem [32][517] fp32; grid Pp/32.
// ---------------------------------------------------------------------------
#define LF_SMEM (32 * 517 * 4)

__global__ __launch_bounds__(256)
void ln_final_kernel(const __half* __restrict__ bt, const __half* __restrict__ res,
                     const float* __restrict__ w1, const float* __restrict__ b1,
                     float* __restrict__ out)
{
    extern __shared__ float S[];   // [32][517]
    const int lane = threadIdx.x & 31;
    const int warp = threadIdx.x >> 5;
    const int pos0 = blockIdx.x * 32;

#pragma unroll 1
    for (int p = 0; p < 4; p++) {
        const int pl = warp * 4 + p;
        const int pos = pos0 + pl;
        const __half* row  = bt  + (size_t)pos * Dm;
        const __half* rrow = res + (size_t)pos * Dm;

        float vals[16];
        float s = 0.f, s2 = 0.f;
#pragma unroll
        for (int k = 0; k < 16; k++) {
            const int c = lane + 32 * k;
            const float v = __half2float(row[c]) + __half2float(rrow[c]);
            vals[k] = v; s += v; s2 += v * v;
        }
#pragma unroll
        for (int o = 16; o; o >>= 1) {
            s  += __shfl_xor_sync(0xffffffffu, s,  o);
            s2 += __shfl_xor_sync(0xffffffffu, s2, o);
        }
        const float mean = s * (1.f / Dm);
        const float var  = s2 * (1.f / Dm) - mean * mean;
        const float rstd = rsqrtf(var + EPS);
#pragma unroll
        for (int k = 0; k < 16; k++) {
            const int c = lane + 32 * k;
            S[pl * 517 + c] = (vals[k] - mean) * rstd * w1[c] + b1[c];
        }
    }
    __syncthreads();

    const int tx = threadIdx.x & 31;     // position
    const int ty = threadIdx.x >> 5;     // channel slice
#pragma unroll 8
    for (int i = 0; i < 64; i++) {
        const int c = ty + 8 * i;
        out[(size_t)c * Pp + pos0 + tx] = S[tx * 517 + c];
    }
}

// ---------------------------------------------------------------------------
// Column attention (fp16 qkv) — output TRANSPOSED [pos][c] fp16 (16B stores).
// Each thread: 2 adjacent l, 4 i-rows. half2 scores + h2exp, fp32 accum.
// ---------------------------------------------------------------------------
__global__ __launch_bounds__(256)
void colattn_kernel(const __half* __restrict__ qkv, __half* __restrict__ outT)
{
    const int h = blockIdx.z;
    const int l2 = blockIdx.x * 32 + 2 * threadIdx.x;   // tx in [0,16)
    const int ty = threadIdx.y;                          // [0,16)
    const __half* Q  = qkv + (size_t)h * Cc * Pp;
    const __half* Kp = Q + (size_t)Dm * Pp;
    const __half* V  = Q + 2L * (size_t)Dm * Pp;

    __half2 q2[4][Cc];
#pragma unroll
    for (int ii = 0; ii < 4; ii++) {
        const int i = ty + 16 * ii;
#pragma unroll
        for (int c = 0; c < Cc; c++)
            q2[ii][c] = *reinterpret_cast<const __half2*>(&Q[(size_t)c * Pp + i * Lm + l2]);
    }

    float d0[4] = {0.f, 0.f, 0.f, 0.f};
    float d1[4] = {0.f, 0.f, 0.f, 0.f};
    float a0[4][Cc], a1[4][Cc];
#pragma unroll
    for (int ii = 0; ii < 4; ii++)
#pragma unroll
        for (int c = 0; c < Cc; c++) { a0[ii][c] = 0.f; a1[ii][c] = 0.f; }

    for (int j = 0; j < Sm; j++) {
        __half2 kv2[Cc];
        float vv0[Cc], vv1[Cc];
#pragma unroll
        for (int c = 0; c < Cc; c++) {
            kv2[c] = *reinterpret_cast<const __half2*>(&Kp[(size_t)c * Pp + j * Lm + l2]);
            const __half2 v2 = *reinterpret_cast<const __half2*>(&V[(size_t)c * Pp + j * Lm + l2]);
            vv0[c] = __low2float(v2);
            vv1[c] = __high2float(v2);
        }
#pragma unroll
        for (int ii = 0; ii < 4; ii++) {
            __half2 s2 = __hmul2(q2[ii][0], kv2[0]);
#pragma unroll
            for (int c = 1; c < Cc; c++) s2 = __hfma2(q2[ii][c], kv2[c], s2);
            const __half2 e2 = h2exp(s2);
            const float e0 = __low2float(e2);
            const float e1 = __high2float(e2);
            d0[ii] += e0; d1[ii] += e1;
#pragma unroll
            for (int c = 0; c < Cc; c++) {
                a0[ii][c] = fmaf(e0, vv0[c], a0[ii][c]);
                a1[ii][c] = fmaf(e1, vv1[c], a1[ii][c]);
            }
        }
    }
#pragma unroll
    for (int ii = 0; ii < 4; ii++) {
        const int i = ty + 16 * ii;
        const float inv0 = 1.f / d0[ii];
        const float inv1 = 1.f / d1[ii];
        __half2 o0[4], o1[4];
#pragma unroll
        for (int c = 0; c < 4; c++) {
            o0[c] = __floats2half2_rn(a0[ii][2 * c] * inv0, a0[ii][2 * c + 1] * inv0);
            o1[c] = __floats2half2_rn(a1[ii][2 * c] * inv1, a1[ii][2 * c + 1] * inv1);
        }
        // transposed: outT[pos * 512 + h*8 + c], pos = i*Lm + l
        __half* p0 = outT + (size_t)(i * Lm + l2)     * Dm + h * Cc;
        __half* p1 = outT + (size_t)(i * Lm + l2 + 1) * Dm + h * Cc;
        *reinterpret_cast<uint4*>(p0) = *reinterpret_cast<uint4*>(o0);
        *reinterpret_cast<uint4*>(p1) = *reinterpret_cast<uint4*>(o1);
    }
}

// ---------------------------------------------------------------------------
// Host side
// ---------------------------------------------------------------------------
extern "C" void kernel_launch(void* const* d_in, const int* in_sizes, int n_in,
                              void* d_out, int out_size)
{
    const float* x     = (const float*)d_in[0];
    const float* w_row = (const float*)d_in[1];
    const float* b_row = (const float*)d_in[2];
    const float* w_col = (const float*)d_in[3];
    const float* b_col = (const float*)d_in[4];
    const float* w_an1 = (const float*)d_in[5];
    const float* b_an1 = (const float*)d_in[6];
    const float* w_an2 = (const float*)d_in[7];
    const float* b_an2 = (const float*)d_in[8];
    const float* w_ff1 = (const float*)d_in[9];
    const float* b_ff1 = (const float*)d_in[10];
    const float* w_ff2 = (const float*)d_in[11];
    const float* b_ff2 = (const float*)d_in[12];
    const float* w_ln1 = (const float*)d_in[13];
    const float* b_ln1 = (const float*)d_in[14];
    const float* w_ln2 = (const float*)d_in[15];
    const float* b_ln2 = (const float*)d_in[16];
    float* outp = (float*)d_out;

    __half *tmph, *qkv16, *bt, *ff, *wr, *wc, *f1, *f2, *qt, *kt, *p16;
    cudaGetSymbolAddress((void**)&tmph,  g_tmph);
    cudaGetSymbolAddress((void**)&qkv16, g_qkv16);
    cudaGetSymbolAddress((void**)&bt,    g_bt);
    cudaGetSymbolAddress((void**)&ff,    g_ff);
    cudaGetSymbolAddress((void**)&wr,    g_wr);
    cudaGetSymbolAddress((void**)&wc,    g_wc);
    cudaGetSymbolAddress((void**)&f1,    g_f1);
    cudaGetSymbolAddress((void**)&f2,    g_f2);
    cudaGetSymbolAddress((void**)&qt,    g_qt);
    cudaGetSymbolAddress((void**)&kt,    g_kt);
    cudaGetSymbolAddress((void**)&p16,   g_p16);

    cudaFuncSetAttribute(gemm_mma<1>, cudaFuncAttributeMaxDynamicSharedMemorySize, MM_SMEM);
    cudaFuncSetAttribute(gemm_mma<2>, cudaFuncAttributeMaxDynamicSharedMemorySize, MM_SMEM);
    cudaFuncSetAttribute(gemm_mma<3>, cudaFuncAttributeMaxDynamicSharedMemorySize, MM_SMEM);
    cudaFuncSetAttribute(gemm_scores, cudaFuncAttributeMaxDynamicSharedMemorySize, SC_SMEM);
    cudaFuncSetAttribute(gemm_vp,     cudaFuncAttributeMaxDynamicSharedMemorySize, MM_SMEM);
    cudaFuncSetAttribute(ln_final_kernel, cudaFuncAttributeMaxDynamicSharedMemorySize, LF_SMEM);

    // merged weight conversion
    convw_all<<<WN4 / 1024, 256>>>(w_row, w_col, w_ff1, w_ff2, wr, wc, f1, f2);

    // x -> transposed fp16
    convt_kernel<<<dim3(Pp / 32, Dm / 32), dim3(32, 8)>>>(x, bt, Dm, Pp);

    // 1) row qkv -> fp16
    gemm_mma<2><<<dim3((3 * Dm) / 128, Pp / 128), 256, MM_SMEM>>>(
        wr, bt, b_row, nullptr, qkv16, 3 * Dm, Pp, Dm);

    // 2) Q/K transpose
    convtqk_kernel<<<dim3(Lm / 64, Dm / 64, 2 * Hh), dim3(32, 8)>>>(qkv16, qt, kt);

    // 3) scores + fused softmax -> P fp16
    gemm_scores<<<dim3(Lm / 64, 1, Hh), 256, SC_SMEM>>>(qt, kt, p16);

    // 4) row_out = V * P^T -> fp16 tmph ([c][pos])
    gemm_vp<<<dim3(4, 2, Hh), 256, MM_SMEM>>>(qkv16 + 2L * Dm * Pp, p16, tmph);

    // 5) out1 = LN(x + row_out; an1) -> bt only
    ln_row_kernel<<<Pp / 32, dim3(32, 8)>>>(x, tmph, w_an1, b_an1, bt);

    // 6) col qkv -> fp16
    gemm_mma<2><<<dim3((3 * Dm) / 128, Pp / 128), 256, MM_SMEM>>>(
        wc, bt, b_col, nullptr, qkv16, 3 * Dm, Pp, Dm);

    // 7) column attention -> fp16 tmph TRANSPOSED [pos][c]
    colattn_kernel<<<dim3(Lm / 32, 1, Hh), dim3(16, 16)>>>(qkv16, tmph);

    // 8+9) h = LN(LN(bt + col_out; an2); ln1), all [pos][c], in-place into bt
    ln_t_kernel<<<Pp / 32, 256>>>(bt, tmph, w_an2, b_an2, w_ln1, b_ln1);

    // 10) ff1: relu(w_ff1 @ h + b_ff1) -> fp16 transposed [Pp][Fm]
    gemm_mma<1><<<dim3(Fm / 128, Pp / 128), 256, MM_SMEM>>>(
        f1, bt, b_ff1, nullptr, ff, Fm, Pp, Dm);

    // 11) ff2 -> fp16 tmph TRANSPOSED [pos][c] (MODE 3)
    gemm_mma<3><<<dim3(Dm / 128, Pp / 128), 256, MM_SMEM>>>(
        f2, ff, b_ff2, nullptr, tmph, Dm, Pp, Fm);

    // 12) out = LN(h + ff2; ln2) -> fp32 [c][pos]
    ln_final_kernel<<<Pp / 32, 256, LF_SMEM>>>(bt, tmph, w_ln2, b_ln2, outp);
}

// round 17
// speedup vs baseline: 1.0347x; 1.0347x over previous
#include <cuda_runtime.h>
#include <cuda_fp16.h>
#include <math_constants.h>
#include <cstdint>
#include <cstddef>

// ---------------------------------------------------------------------------
// Problem constants
// ---------------------------------------------------------------------------
#define Dm   512
#define Sm   64
#define Lm   256
#define Fm   2048
#define Hh   64
#define Cc   8
#define Pp   (Sm * Lm)          // 16384 spatial positions
#define EPS  1e-5f

// ---------------------------------------------------------------------------
// Scratch buffers (static device globals -- allocation-free)
// ---------------------------------------------------------------------------
__device__ __align__(256) float  g_out1[(long)Dm * Pp];
__device__ __align__(256) __half g_tmph[(long)Dm * Pp];      // row_out / col_out / ff2 (fp16)

// fp16 operands (all single-plane)
__device__ __align__(256) __half g_qkv16[3L * Dm * Pp];      // qkv fp16 [1536][16384]
__device__ __align__(256) __half g_bt [(long)Pp * Dm];       // act^T [Pp,512]
__device__ __align__(256) __half g_ff [(long)Pp * Fm];       // ff1^T [Pp,2048]
__device__ __align__(256) __half g_wr [3 * Dm * Dm];
__device__ __align__(256) __half g_wc [3 * Dm * Dm];
__device__ __align__(256) __half g_f1 [Fm * Dm];
__device__ __align__(256) __half g_f2 [Dm * Fm];
__device__ __align__(256) __half g_qt [(long)Hh * Lm * Dm];  // Q^T per head
__device__ __align__(256) __half g_kt [(long)Hh * Lm * Dm];  // K^T per head
__device__ __align__(256) __half g_p16[(long)Hh * Lm * Lm];  // P [h][i][j]

// ---------------------------------------------------------------------------
// PTX helpers
// ---------------------------------------------------------------------------
__device__ __forceinline__ uint32_t smem_u32(const void* p) {
    uint32_t a;
    asm("{ .reg .u64 t; cvta.to.shared.u64 t, %1; cvt.u32.u64 %0, t; }" : "=r"(a) : "l"(p));
    return a;
}
__device__ __forceinline__ void cpasync16(uint32_t dst, const void* src) {
    asm volatile("cp.async.cg.shared.global [%0], [%1], 16;" :: "r"(dst), "l"(src));
}
__device__ __forceinline__ void cp_commit() {
    asm volatile("cp.async.commit_group;" ::: "memory");
}
template<int N>
__device__ __forceinline__ void cp_wait() {
    asm volatile("cp.async.wait_group %0;" :: "n"(N) : "memory");
}
__device__ __forceinline__ void ldsm4(uint32_t* r, uint32_t addr) {
    asm volatile("ldmatrix.sync.aligned.m8n8.x4.shared.b16 {%0,%1,%2,%3}, [%4];"
                 : "=r"(r[0]), "=r"(r[1]), "=r"(r[2]), "=r"(r[3]) : "r"(addr));
}
__device__ __forceinline__ void mma16816h(float* d, const uint32_t* a, uint32_t b0, uint32_t b1) {
    asm volatile("mma.sync.aligned.m16n8k16.row.col.f32.f16.f16.f32 "
                 "{%0,%1,%2,%3}, {%4,%5,%6,%7}, {%8,%9}, {%0,%1,%2,%3};"
                 : "+f"(d[0]), "+f"(d[1]), "+f"(d[2]), "+f"(d[3])
                 : "r"(a[0]), "r"(a[1]), "r"(a[2]), "r"(a[3]), "r"(b0), "r"(b1));
}

// ---------------------------------------------------------------------------
// Big GEMM: C[M,N] = W[M,K] * B[N,K]^T (+bias), single fp16 pass.
// CTA tile 128x128, BK=64, 3-stage ring (96KB), 8 warps (4m x 2n), 2 CTAs/SM.
//   MODE 0: C fp32 [M,N] + bias.
//   MODE 1: relu(+bias) -> fp16 transposed [N,M].
//   MODE 2: fp16 [M,N] + bias.
// ---------------------------------------------------------------------------
#define MM_SBYTES 32768u
#define MM_SMEM   (3 * MM_SBYTES)

template<int MODE>
__global__ void __launch_bounds__(256, 2)
gemm_mma(const __half* __restrict__ A, const __half* __restrict__ B,
         const float* __restrict__ bias,
         float* __restrict__ C, __half* __restrict__ oH,
         int M, int N, int K)
{
    extern __shared__ char smem[];
    const uint32_t sb = smem_u32(smem);

    const int tid  = threadIdx.x;
    const int wid  = tid >> 5;
    const int lane = tid & 31;
    const int warpM = wid & 3;
    const int warpN = wid >> 2;
    const int bm = blockIdx.x * 128;
    const int bn = blockIdx.y * 128;

    auto load_stage = [&](int st, int it) {
        const uint32_t sbase = sb + st * MM_SBYTES;
        const int k0 = it << 6;
#pragma unroll
        for (int j = 0; j < 4; j++) {
            const int idx = tid + j * 256;
            const int row = idx >> 3;
            const int c   = idx & 7;
            const uint32_t soff = row * 128 + ((c * 16) ^ ((row & 7) << 4));
            cpasync16(sbase +         soff, A + (size_t)(bm + row) * K + k0 + c * 8);
            cpasync16(sbase + 16384 + soff, B + (size_t)(bn + row) * K + k0 + c * 8);
        }
    };

    float acc[2][8][4];
#pragma unroll
    for (int i = 0; i < 2; i++)
#pragma unroll
        for (int j = 0; j < 8; j++)
#pragma unroll
            for (int v = 0; v < 4; v++) acc[i][j][v] = 0.f;

    const int nIter = K >> 6;
    load_stage(0, 0); cp_commit();
    load_stage(1, 1); cp_commit();

    const int rsub  = lane & 15;
    const int khalf = ((lane >> 4) & 1) * 16;
    const int rA = warpM * 32 + rsub;
    const int rB = warpN * 64 + rsub;
    const uint32_t xA = (rA & 7) << 4;
    const uint32_t xB = (rB & 7) << 4;

    for (int it = 0; it < nIter; it++) {
        cp_wait<1>();
        __syncthreads();
        if (it + 2 < nIter) load_stage((it + 2) % 3, it + 2);
        cp_commit();

        const uint32_t sbase = sb + (it % 3) * MM_SBYTES;
        const uint32_t pA = sbase +         rA * 128;
        const uint32_t pB = sbase + 16384 + rB * 128;

#pragma unroll
        for (int q = 0; q < 4; q++) {
            const uint32_t kb = q * 32 + khalf;
            uint32_t ah[2][4], bb[4][4];
#pragma unroll
            for (int mt = 0; mt < 2; mt++)
                ldsm4(ah[mt], pA + mt * 2048 + (kb ^ xA));
#pragma unroll
            for (int g = 0; g < 4; g++)
                ldsm4(bb[g], pB + g * 2048 + (kb ^ xB));
#pragma unroll
            for (int mt = 0; mt < 2; mt++)
#pragma unroll
                for (int nt = 0; nt < 8; nt++) {
                    const int g = nt >> 1, o = nt & 1;
                    mma16816h(acc[mt][nt], ah[mt], bb[g][o], bb[g][o + 2]);
                }
        }
    }
    cp_wait<0>();
    __syncthreads();

    if (MODE == 0) {
#pragma unroll
        for (int mt = 0; mt < 2; mt++) {
            const int r0 = bm + warpM * 32 + mt * 16 + (lane >> 2);
            const float bv0 = bias[r0], bv1 = bias[r0 + 8];
#pragma unroll
            for (int nt = 0; nt < 8; nt++) {
                const int c0 = bn + warpN * 64 + nt * 8 + (lane & 3) * 2;
                float* d = acc[mt][nt];
                *reinterpret_cast<float2*>(&C[(size_t)r0 * N + c0])       = make_float2(d[0] + bv0, d[1] + bv0);
                *reinterpret_cast<float2*>(&C[(size_t)(r0 + 8) * N + c0]) = make_float2(d[2] + bv1, d[3] + bv1);
            }
        }
    } else if (MODE == 2) {
#pragma unroll
        for (int mt = 0; mt < 2; mt++) {
            const int r0 = bm + warpM * 32 + mt * 16 + (lane >> 2);
            const float bv0 = bias[r0], bv1 = bias[r0 + 8];
#pragma unroll
            for (int nt = 0; nt < 8; nt++) {
                const int c0 = bn + warpN * 64 + nt * 8 + (lane & 3) * 2;
                float* d = acc[mt][nt];
                *reinterpret_cast<__half2*>(&oH[(size_t)r0 * N + c0])       = __floats2half2_rn(d[0] + bv0, d[1] + bv0);
                *reinterpret_cast<__half2*>(&oH[(size_t)(r0 + 8) * N + c0]) = __floats2half2_rn(d[2] + bv1, d[3] + bv1);
            }
        }
    } else {
        float* T = reinterpret_cast<float*>(smem);   // [128][130]
#pragma unroll
        for (int mt = 0; mt < 2; mt++) {
            const int lr0 = warpM * 32 + mt * 16 + (lane >> 2);
            const float bv0 = bias[bm + lr0], bv1 = bias[bm + lr0 + 8];
#pragma unroll
            for (int nt = 0; nt < 8; nt++) {
                const int lc0 = warpN * 64 + nt * 8 + (lane & 3) * 2;
                float* d = acc[mt][nt];
                T[lr0 * 130 + lc0]           = fmaxf(d[0] + bv0, 0.f);
                T[lr0 * 130 + lc0 + 1]       = fmaxf(d[1] + bv0, 0.f);
                T[(lr0 + 8) * 130 + lc0]     = fmaxf(d[2] + bv1, 0.f);
                T[(lr0 + 8) * 130 + lc0 + 1] = fmaxf(d[3] + bv1, 0.f);
            }
        }
        __syncthreads();
        const int mloc = tid & 127;
#pragma unroll 4
        for (int rep = 0; rep < 64; rep++) {
            const int nl = rep * 2 + (tid >> 7);
            oH[(size_t)(bn + nl) * M + bm + mloc] = __float2half(T[mloc * 130 + nl]);
        }
    }
}

// ---------------------------------------------------------------------------
// Row-attention scores + FUSED softmax: per head tile 64(i) x 256(j), K=512.
// 2-stage ring (80KB) -> 2 CTAs/SM.
// ---------------------------------------------------------------------------
#define SC_SBYTES 40960u
#define SC_SMEM   (2 * SC_SBYTES)

__global__ void __launch_bounds__(256, 2)
gemm_scores(const __half* __restrict__ Q, const __half* __restrict__ Kt,
            __half* __restrict__ P)
{
    constexpr int K = 512;
    extern __shared__ char smem[];
    const uint32_t sb = smem_u32(smem);

    const int tid = threadIdx.x, wid = tid >> 5, lane = tid & 31;
    const int warpM = wid & 3;
    const int warpN = wid >> 2;
    const int bm = blockIdx.x * 64;
    const int h = blockIdx.z;
    const __half* A = Q  + (size_t)h * Lm * Dm;
    const __half* B = Kt + (size_t)h * Lm * Dm;

    auto load_stage = [&](int st, int it) {
        const uint32_t sbase = sb + st * SC_SBYTES;
        const int k0 = it << 6;
#pragma unroll
        for (int j = 0; j < 10; j++) {
            const int idx = tid + j * 256;
            if (idx < 512) {
                const int row = idx >> 3, c = idx & 7;
                const uint32_t soff = row * 128 + ((c * 16) ^ ((row & 7) << 4));
                cpasync16(sbase + soff, A + (size_t)(bm + row) * K + k0 + c * 8);
            } else {
                const int i2 = idx - 512;
                const int row = i2 >> 3, c = i2 & 7;
                const uint32_t soff = row * 128 + ((c * 16) ^ ((row & 7) << 4));
                cpasync16(sbase + 8192 + soff, B + (size_t)row * K + k0 + c * 8);
            }
        }
    };

    float acc[16][4];
#pragma unroll
    for (int j = 0; j < 16; j++)
#pragma unroll
        for (int v = 0; v < 4; v++) acc[j][v] = 0.f;

    load_stage(0, 0); cp_commit();
    load_stage(1, 1); cp_commit();

    const int rsub  = lane & 15;
    const int khalf = ((lane >> 4) & 1) * 16;
    const int rA = warpM * 16 + rsub;
    const int rBb = warpN * 128 + rsub;
    const uint32_t xs = (rsub & 7) << 4;

    for (int it = 0; it < 8; it++) {
        cp_wait<1>();
        __syncthreads();

        const uint32_t sbase = sb + (it & 1) * SC_SBYTES;
        const uint32_t pA = sbase +        rA  * 128;
        const uint32_t pB = sbase + 8192 + rBb * 128;

#pragma unroll
        for (int q = 0; q < 4; q++) {
            const uint32_t kb = q * 32 + khalf;
            uint32_t ah[4], bb[8][4];
            ldsm4(ah, pA + (kb ^ xs));
#pragma unroll
            for (int g = 0; g < 8; g++)
                ldsm4(bb[g], pB + g * 2048 + (kb ^ xs));
#pragma unroll
            for (int nt = 0; nt < 16; nt++) {
                const int g = nt >> 1, o = nt & 1;
                mma16816h(acc[nt], ah, bb[g][o], bb[g][o + 2]);
            }
        }
        __syncthreads();
        if (it + 2 < 8) { load_stage(it & 1, it + 2); }
        cp_commit();
    }
    cp_wait<0>();
    __syncthreads();

    float* S = reinterpret_cast<float*>(smem);
    {
        const int r0 = warpM * 16 + (lane >> 2);
#pragma unroll
        for (int nt = 0; nt < 16; nt++) {
            const int c0 = warpN * 128 + nt * 8 + (lane & 3) * 2;
            float* d = acc[nt];
            S[r0 * 260 + c0]           = d[0];
            S[r0 * 260 + c0 + 1]       = d[1];
            S[(r0 + 8) * 260 + c0]     = d[2];
            S[(r0 + 8) * 260 + c0 + 1] = d[3];
        }
    }
    __syncthreads();

#pragma unroll
    for (int rr = 0; rr < 8; rr++) {
        const int r = wid * 8 + rr;
        float v[8];
#pragma unroll
        for (int k = 0; k < 8; k++) v[k] = S[r * 260 + lane + 32 * k];
        float m = v[0];
#pragma unroll
        for (int k = 1; k < 8; k++) m = fmaxf(m, v[k]);
#pragma unroll
        for (int o = 16; o; o >>= 1) m = fmaxf(m, __shfl_xor_sync(0xffffffffu, m, o));
        float s = 0.f;
#pragma unroll
        for (int k = 0; k < 8; k++) { v[k] = __expf(v[k] - m); s += v[k]; }
#pragma unroll
        for (int o = 16; o; o >>= 1) s += __shfl_xor_sync(0xffffffffu, s, o);
        const float inv = 1.f / s;
        __half* dst = P + ((size_t)h * Lm + bm + r) * Lm;
#pragma unroll
        for (int k = 0; k < 8; k++) dst[lane + 32 * k] = __float2half(v[k] * inv);
    }
}

// ---------------------------------------------------------------------------
// Row-attention output: per head, C[m=(c,s), i] = sum_j V[m,j] * P[i,j]. fp16 out.
// ---------------------------------------------------------------------------
__global__ void __launch_bounds__(256, 2)
gemm_vp(const __half* __restrict__ V, const __half* __restrict__ P,
        __half* __restrict__ O)
{
    constexpr int K = 256;
    extern __shared__ char smem[];
    const uint32_t sb = smem_u32(smem);

    const int tid = threadIdx.x, wid = tid >> 5, lane = tid & 31;
    const int warpM = wid & 3, warpN = wid >> 2;
    const int bm = blockIdx.x * 128, bn = blockIdx.y * 128;
    const int h = blockIdx.z;
    const __half* Av = V + (size_t)h * 8 * Pp;
    const __half* Bp = P + (size_t)h * Lm * Lm;
    __half* C = O + (size_t)h * 8 * Pp;

    auto load_stage = [&](int st, int it) {
        const uint32_t sbase = sb + st * MM_SBYTES;
        const int k0 = it << 6;
#pragma unroll
        for (int j = 0; j < 4; j++) {
            const int idx = tid + j * 256;
            const int row = idx >> 3;
            const int c   = idx & 7;
            const uint32_t soff = row * 128 + ((c * 16) ^ ((row & 7) << 4));
            const int mrow = bm + row;
            const size_t ga = (size_t)(mrow >> 6) * Pp + (mrow & 63) * 256 + k0 + c * 8;
            cpasync16(sbase +         soff, Av + ga);
            cpasync16(sbase + 16384 + soff, Bp + (size_t)(bn + row) * K + k0 + c * 8);
        }
    };

    float acc[2][8][4];
#pragma unroll
    for (int i = 0; i < 2; i++)
#pragma unroll
        for (int j = 0; j < 8; j++)
#pragma unroll
            for (int v = 0; v < 4; v++) acc[i][j][v] = 0.f;

    load_stage(0, 0); cp_commit();
    load_stage(1, 1); cp_commit();

    const int rsub  = lane & 15;
    const int khalf = ((lane >> 4) & 1) * 16;
    const int rA = warpM * 32 + rsub;
    const int rB = warpN * 64 + rsub;
    const uint32_t xA = (rA & 7) << 4;
    const uint32_t xB = (rB & 7) << 4;

    for (int it = 0; it < 4; it++) {
        cp_wait<1>();
        __syncthreads();
        if (it + 2 < 4) load_stage((it + 2) % 3, it + 2);
        cp_commit();

        const uint32_t sbase = sb + (it % 3) * MM_SBYTES;
        const uint32_t pA = sbase +         rA * 128;
        const uint32_t pB = sbase + 16384 + rB * 128;

#pragma unroll
        for (int q = 0; q < 4; q++) {
            const uint32_t kb = q * 32 + khalf;
            uint32_t av[2][4], bb[4][4];
#pragma unroll
            for (int mt = 0; mt < 2; mt++)
                ldsm4(av[mt], pA + mt * 2048 + (kb ^ xA));
#pragma unroll
            for (int g = 0; g < 4; g++)
                ldsm4(bb[g], pB + g * 2048 + (kb ^ xB));
#pragma unroll
            for (int mt = 0; mt < 2; mt++)
#pragma unroll
                for (int nt = 0; nt < 8; nt++) {
                    const int g = nt >> 1, o = nt & 1;
                    mma16816h(acc[mt][nt], av[mt], bb[g][o], bb[g][o + 2]);
                }
        }
    }
    cp_wait<0>();
    __syncthreads();

#pragma unroll
    for (int mt = 0; mt < 2; mt++) {
        const int r0 = bm + warpM * 32 + mt * 16 + (lane >> 2);
        const int r1 = r0 + 8;
        const size_t a0 = (size_t)(r0 >> 6) * Pp + (r0 & 63) * 256;
        const size_t a1 = (size_t)(r1 >> 6) * Pp + (r1 & 63) * 256;
#pragma unroll
        for (int nt = 0; nt < 8; nt++) {
            const int c0 = bn + warpN * 64 + nt * 8 + (lane & 3) * 2;
            float* d = acc[mt][nt];
            *reinterpret_cast<__half2*>(&C[a0 + c0]) = __floats2half2_rn(d[0], d[1]);
            *reinterpret_cast<__half2*>(&C[a1 + c0]) = __floats2half2_rn(d[2], d[3]);
        }
    }
}

// ---------------------------------------------------------------------------
// Merged prep: weight conversion (4 matrices) + x transpose-convert, ONE launch.
// Blocks [0, WNB): weights (float4-vectorized). Blocks [WNB, WNB+CTB): convt.
// ---------------------------------------------------------------------------
#define WN1 (3 * Dm * Dm)
#define WN2 (2 * WN1)
#define WN3 (WN2 + Fm * Dm)
#define WN4 (WN3 + Dm * Fm)
#define WNB (WN4 / 1024)                 // 3584 weight blocks
#define CTB ((Pp / 32) * (Dm / 32))      // 8192 convt blocks

__global__ void __launch_bounds__(256)
prep_kernel(const float* __restrict__ w_row, const float* __restrict__ w_col,
            const float* __restrict__ wf1, const float* __restrict__ wf2,
            __half* __restrict__ owr, __half* __restrict__ owc,
            __half* __restrict__ of1, __half* __restrict__ of2,
            const float* __restrict__ x, __half* __restrict__ obt)
{
    __shared__ float t[32][33];
    if (blockIdx.x < WNB) {
        const long i = ((long)blockIdx.x * 256 + threadIdx.x) * 4;
        const float* src; __half* dst; long off;
        if (i < WN1)      { src = w_row; dst = owr; off = 0; }
        else if (i < WN2) { src = w_col; dst = owc; off = WN1; }
        else if (i < WN3) { src = wf1;   dst = of1; off = WN2; }
        else              { src = wf2;   dst = of2; off = WN3; }
        const long j = i - off;
        const float4 v = *reinterpret_cast<const float4*>(src + j);
        *reinterpret_cast<__half2*>(dst + j)     = __floats2half2_rn(v.x, v.y);
        *reinterpret_cast<__half2*>(dst + j + 2) = __floats2half2_rn(v.z, v.w);
    } else {
        // transpose-convert x fp32 [Dm][Pp] -> fp16 [Pp][Dm]
        const int idx = blockIdx.x - WNB;
        const int n0 = (idx & (Pp / 32 - 1)) * 32;     // position tile
        const int k0 = (idx / (Pp / 32)) * 32;         // channel tile
        const int tx = threadIdx.x & 31, ty = threadIdx.x >> 5;  // 32 x 8
#pragma unroll
        for (int i = 0; i < 4; i++)
            t[ty + 8 * i][tx] = x[(size_t)(k0 + ty + 8 * i) * Pp + n0 + tx];
        __syncthreads();
#pragma unroll
        for (int i = 0; i < 4; i++) {
            const int r = ty + 8 * i;
            obt[(size_t)(n0 + r) * Dm + k0 + tx] = __float2half(t[tx][r]);
        }
    }
}

// Q/K per-head transpose (fp16 in, fp16 out) — half2 vectorized, 64x64 tiles.
__global__ void __launch_bounds__(256)
convtqk_kernel(const __half* __restrict__ qkv,
               __half* __restrict__ qo, __half* __restrict__ ko)
{
    __shared__ __half t[64][66];       // [l_local][k_local]
    const int h = blockIdx.z >> 1;
    const int isK = blockIdx.z & 1;
    const __half* in = qkv + (isK ? (size_t)Dm * Pp : 0) + (size_t)h * 8 * Pp;
    __half* o = (isK ? ko : qo) + (size_t)h * Lm * Dm;
    const int l0 = blockIdx.x * 64, k0 = blockIdx.y * 64;
    const int tx = threadIdx.x, ty = threadIdx.y;   // 32 x 8
#pragma unroll
    for (int i = 0; i < 8; i++) {
        const int k = k0 + ty + 8 * i;
        const __half2 v = *reinterpret_cast<const __half2*>(
            &in[(size_t)(k >> 6) * Pp + (k & 63) * 256 + l0 + 2 * tx]);
        t[2 * tx][ty + 8 * i]     = __low2half(v);
        t[2 * tx + 1][ty + 8 * i] = __high2half(v);
    }
    __syncthreads();
#pragma unroll
    for (int i = 0; i < 8; i++) {
        const int r = ty + 8 * i;
        *reinterpret_cast<__half2*>(&o[(size_t)(l0 + r) * Dm + k0 + 2 * tx]) =
            *reinterpret_cast<const __half2*>(&t[r][2 * tx]);
    }
}

// ---------------------------------------------------------------------------
// Channel LayerNorm over D=512: vals = in(fp32) + res(fp16); LN(w1,b1);
// if DOUBLE, a second LN(w2,b2) on the result. Optional fp32 out + fp16^T out.
// ---------------------------------------------------------------------------
template<bool DOUBLE>
__global__ __launch_bounds__(256)
void ln_kernel(const float* __restrict__ in, const __half* __restrict__ res,
               const float* __restrict__ w1, const float* __restrict__ b1,
               const float* __restrict__ w2, const float* __restrict__ b2,
               float* __restrict__ out, __half* __restrict__ obt)
{
    __shared__ float ss[8][32], ss2[8][32];
    __shared__ __half tbuf[32][514];
    const int tx = threadIdx.x, ty = threadIdx.y;
    const int tid = ty * 32 + tx;
    const int pos0 = blockIdx.x * 32;
    const int pos = pos0 + tx;

    float vals[64];
    float s = 0.f, s2 = 0.f;
#pragma unroll
    for (int i = 0; i < 64; i++) {
        const int c = ty + 8 * i;
        float v = in[(size_t)c * Pp + pos];
        if (res) v += __half2float(res[(size_t)c * Pp + pos]);
        vals[i] = v; s += v; s2 += v * v;
    }
    ss[ty][tx] = s; ss2[ty][tx] = s2;
    __syncthreads();
    {
        float st = 0.f, st2 = 0.f;
#pragma unroll
        for (int y = 0; y < 8; y++) { st += ss[y][tx]; st2 += ss2[y][tx]; }
        const float mean = st * (1.f / Dm);
        const float var  = st2 * (1.f / Dm) - mean * mean;
        const float rstd = rsqrtf(var + EPS);
#pragma unroll
        for (int i = 0; i < 64; i++) {
            const int c = ty + 8 * i;
            vals[i] = (vals[i] - mean) * rstd * w1[c] + b1[c];
        }
    }
    if (DOUBLE) {
        float t = 0.f, t2 = 0.f;
#pragma unroll
        for (int i = 0; i < 64; i++) { t += vals[i]; t2 += vals[i] * vals[i]; }
        __syncthreads();
        ss[ty][tx] = t; ss2[ty][tx] = t2;
        __syncthreads();
        float st = 0.f, st2 = 0.f;
#pragma unroll
        for (int y = 0; y < 8; y++) { st += ss[y][tx]; st2 += ss2[y][tx]; }
        const float mean = st * (1.f / Dm);
        const float var  = st2 * (1.f / Dm) - mean * mean;
        const float rstd = rsqrtf(var + EPS);
#pragma unroll
        for (int i = 0; i < 64; i++) {
            const int c = ty + 8 * i;
            vals[i] = (vals[i] - mean) * rstd * w2[c] + b2[c];
        }
    }
#pragma unroll
    for (int i = 0; i < 64; i++) {
        const int c = ty + 8 * i;
        out[(size_t)c * Pp + pos] = vals[i];
        if (obt) tbuf[tx][c] = __float2half(vals[i]);
    }
    if (obt) {
        __syncthreads();
#pragma unroll 4
        for (int r = 0; r < 32; r++) {
            const uint32_t val = *reinterpret_cast<const uint32_t*>(&tbuf[r][tid * 2]);
            *reinterpret_cast<uint32_t*>(&obt[(size_t)(pos0 + r) * Dm + tid * 2]) = val;
        }
    }
}

// ---------------------------------------------------------------------------
// Column attention (fp16 qkv) — fp16 out. Each thread: 2 adjacent l, 4 i-rows.
// Scores natively in half2 (HFMA2), exp via h2exp on half2, fp32 accumulators.
// ---------------------------------------------------------------------------
__global__ __launch_bounds__(256)
void colattn_kernel(const __half* __restrict__ qkv, __half* __restrict__ out)
{
    const int h = blockIdx.z;
    const int l2 = blockIdx.x * 32 + 2 * threadIdx.x;   // tx in [0,16)
    const int ty = threadIdx.y;                          // [0,16)
    const __half* Q  = qkv + (size_t)h * Cc * Pp;
    const __half* Kp = Q + (size_t)Dm * Pp;
    const __half* V  = Q + 2L * (size_t)Dm * Pp;

    __half2 q2[4][Cc];
#pragma unroll
    for (int ii = 0; ii < 4; ii++) {
        const int i = ty + 16 * ii;
#pragma unroll
        for (int c = 0; c < Cc; c++)
            q2[ii][c] = *reinterpret_cast<const __half2*>(&Q[(size_t)c * Pp + i * Lm + l2]);
    }

    float d0[4] = {0.f, 0.f, 0.f, 0.f};
    float d1[4] = {0.f, 0.f, 0.f, 0.f};
    float a0[4][Cc], a1[4][Cc];
#pragma unroll
    for (int ii = 0; ii < 4; ii++)
#pragma unroll
        for (int c = 0; c < Cc; c++) { a0[ii][c] = 0.f; a1[ii][c] = 0.f; }

    for (int j = 0; j < Sm; j++) {
        __half2 kv2[Cc];
        float vv0[Cc], vv1[Cc];
#pragma unroll
        for (int c = 0; c < Cc; c++) {
            kv2[c] = *reinterpret_cast<const __half2*>(&Kp[(size_t)c * Pp + j * Lm + l2]);
            const __half2 v2 = *reinterpret_cast<const __half2*>(&V[(size_t)c * Pp + j * Lm + l2]);
            vv0[c] = __low2float(v2);
            vv1[c] = __high2float(v2);
        }
#pragma unroll
        for (int ii = 0; ii < 4; ii++) {
            __half2 s2 = __hmul2(q2[ii][0], kv2[0]);
#pragma unroll
            for (int c = 1; c < Cc; c++) s2 = __hfma2(q2[ii][c], kv2[c], s2);
            const __half2 e2 = h2exp(s2);
            const float e0 = __low2float(e2);
            const float e1 = __high2float(e2);
            d0[ii] += e0; d1[ii] += e1;
#pragma unroll
            for (int c = 0; c < Cc; c++) {
                a0[ii][c] = fmaf(e0, vv0[c], a0[ii][c]);
                a1[ii][c] = fmaf(e1, vv1[c], a1[ii][c]);
            }
        }
    }
#pragma unroll
    for (int ii = 0; ii < 4; ii++) {
        const int i = ty + 16 * ii;
        const float inv0 = 1.f / d0[ii];
        const float inv1 = 1.f / d1[ii];
#pragma unroll
        for (int c = 0; c < Cc; c++)
            *reinterpret_cast<__half2*>(&out[(size_t)(h * Cc + c) * Pp + i * Lm + l2]) =
                __floats2half2_rn(a0[ii][c] * inv0, a1[ii][c] * inv1);
    }
}

// ---------------------------------------------------------------------------
// Host side
// ---------------------------------------------------------------------------
extern "C" void kernel_launch(void* const* d_in, const int* in_sizes, int n_in,
                              void* d_out, int out_size)
{
    const float* x     = (const float*)d_in[0];
    const float* w_row = (const float*)d_in[1];
    const float* b_row = (const float*)d_in[2];
    const float* w_col = (const float*)d_in[3];
    const float* b_col = (const float*)d_in[4];
    const float* w_an1 = (const float*)d_in[5];
    const float* b_an1 = (const float*)d_in[6];
    const float* w_an2 = (const float*)d_in[7];
    const float* b_an2 = (const float*)d_in[8];
    const float* w_ff1 = (const float*)d_in[9];
    const float* b_ff1 = (const float*)d_in[10];
    const float* w_ff2 = (const float*)d_in[11];
    const float* b_ff2 = (const float*)d_in[12];
    const float* w_ln1 = (const float*)d_in[13];
    const float* b_ln1 = (const float*)d_in[14];
    const float* w_ln2 = (const float*)d_in[15];
    const float* b_ln2 = (const float*)d_in[16];
    float* outp = (float*)d_out;

    float *out1;
    __half *tmph, *qkv16, *bt, *ff, *wr, *wc, *f1, *f2, *qt, *kt, *p16;
    cudaGetSymbolAddress((void**)&out1,  g_out1);
    cudaGetSymbolAddress((void**)&tmph,  g_tmph);
    cudaGetSymbolAddress((void**)&qkv16, g_qkv16);
    cudaGetSymbolAddress((void**)&bt,    g_bt);
    cudaGetSymbolAddress((void**)&ff,    g_ff);
    cudaGetSymbolAddress((void**)&wr,    g_wr);
    cudaGetSymbolAddress((void**)&wc,    g_wc);
    cudaGetSymbolAddress((void**)&f1,    g_f1);
    cudaGetSymbolAddress((void**)&f2,    g_f2);
    cudaGetSymbolAddress((void**)&qt,    g_qt);
    cudaGetSymbolAddress((void**)&kt,    g_kt);
    cudaGetSymbolAddress((void**)&p16,   g_p16);

    cudaFuncSetAttribute(gemm_mma<0>, cudaFuncAttributeMaxDynamicSharedMemorySize, MM_SMEM);
    cudaFuncSetAttribute(gemm_mma<1>, cudaFuncAttributeMaxDynamicSharedMemorySize, MM_SMEM);
    cudaFuncSetAttribute(gemm_mma<2>, cudaFuncAttributeMaxDynamicSharedMemorySize, MM_SMEM);
    cudaFuncSetAttribute(gemm_scores, cudaFuncAttributeMaxDynamicSharedMemorySize, SC_SMEM);
    cudaFuncSetAttribute(gemm_vp,     cudaFuncAttributeMaxDynamicSharedMemorySize, MM_SMEM);

    // 0) merged prep: weight conversion + x transpose (single launch)
    prep_kernel<<<WNB + CTB, 256>>>(w_row, w_col, w_ff1, w_ff2, wr, wc, f1, f2, x, bt);

    // 1) row qkv -> fp16
    gemm_mma<2><<<dim3((3 * Dm) / 128, Pp / 128), 256, MM_SMEM>>>(
        wr, bt, b_row, nullptr, qkv16, 3 * Dm, Pp, Dm);

    // 2) Q/K transpose
    convtqk_kernel<<<dim3(Lm / 64, Dm / 64, 2 * Hh), dim3(32, 8)>>>(qkv16, qt, kt);

    // 3) scores + fused softmax -> P fp16
    gemm_scores<<<dim3(Lm / 64, 1, Hh), 256, SC_SMEM>>>(qt, kt, p16);

    // 4) row_out = V * P^T -> fp16 tmph
    gemm_vp<<<dim3(4, 2, Hh), 256, MM_SMEM>>>(qkv16 + 2L * Dm * Pp, p16, tmph);

    // 5) out1 = LN(x + row_out; an1), + bt
    ln_kernel<false><<<Pp / 32, dim3(32, 8)>>>(x, tmph, w_an1, b_an1, nullptr, nullptr, out1, bt);

    // 6) col qkv -> fp16
    gemm_mma<2><<<dim3((3 * Dm) / 128, Pp / 128), 256, MM_SMEM>>>(
        wc, bt, b_col, nullptr, qkv16, 3 * Dm, Pp, Dm);

    // 7) column attention -> fp16 tmph (half2 scores, 2 l per thread)
    colattn_kernel<<<dim3(Lm / 32, 1, Hh), dim3(16, 16)>>>(qkv16, tmph);

    // 8+9) h = LN(LN(out1 + col_out; an2); ln1) fused, + bt. out1 overwritten with h.
    ln_kernel<true><<<Pp / 32, dim3(32, 8)>>>(out1, tmph, w_an2, b_an2, w_ln1, b_ln1, out1, bt);

    // 10) ff1: relu(w_ff1 @ h + b_ff1) -> fp16 transposed
    gemm_mma<1><<<dim3(Fm / 128, Pp / 128), 256, MM_SMEM>>>(
        f1, bt, b_ff1, nullptr, ff, Fm, Pp, Dm);

    // 11) ff2 -> fp16 tmph
    gemm_mma<2><<<dim3(Dm / 128, Pp / 128), 256, MM_SMEM>>>(
        f2, ff, b_ff2, nullptr, tmph, Dm, Pp, Fm);

    // 12) out = LN(h + ff2; ln2)
    ln_kernel<false><<<Pp / 32, dim3(32, 8)>>>(out1, tmph, w_ln2, b_ln2, nullptr, nullptr, outp, nullptr);
}